// round 6
// baseline (speedup 1.0000x reference)
#include <cuda_runtime.h>

// ConvBertLightConv: dynamic depthwise conv, kernel=9, head=64.
// inputs:  [B=8, S=4096, D=768] fp32, filters: [B,S,108] fp32, out: [B,S,768].
//
// R5: completely barrier-free kernel. No smem, no __syncthreads, no cp.async
// drains. Each thread redundantly computes the softmax for its own 2 output
// positions in registers (filter taps broadcast-read through L1 by the 16
// column-threads sharing a position group). All warps are independently
// issuable for their whole lifetime -> no synchronized DRAM-queue droughts.
// Input 9x reuse is served by L1 (per-CTA working set ~19KB).

#define S_LEN   4096
#define D_DIM   768
#define H_NUM   12
#define HD      64
#define KS      9
#define TILE_S  64
#define SREG    2
#define NTHREADS 512                 // (TILE_S/SREG) * 16 float4-columns
#define ROW_F4  (D_DIM / 4)          // 192

__global__ __launch_bounds__(NTHREADS, 2)
void lightconv_kernel(const float* __restrict__ inputs,
                      const float* __restrict__ filters,
                      float* __restrict__ out)
{
    const int tid = threadIdx.x;
    const int s0  = blockIdx.x * TILE_S;
    const int h   = blockIdx.y;
    const int b   = blockIdx.z;

    const int c   = tid & 15;                 // float4 column 0..15
    const int sl0 = (tid >> 4) * SREG;        // local base position 0..62

    // ---- per-thread softmax weights for its SREG positions (registers) ----
    // Lanes 0..15 of each half-warp read identical addresses -> L1 broadcast.
    float w[SREG][KS];
    {
        const float* f0 = filters
            + (size_t)(b * S_LEN + s0 + sl0) * (H_NUM * KS) + h * KS;
        #pragma unroll
        for (int i = 0; i < SREG; i++) {
            const float* f = f0 + i * (H_NUM * KS);
            float m = -1e30f;
            #pragma unroll
            for (int k = 0; k < KS; k++) {
                w[i][k] = __ldg(f + k);
                m = fmaxf(m, w[i][k]);
            }
            float sum = 0.f;
            #pragma unroll
            for (int k = 0; k < KS; k++) {
                w[i][k] = __expf(w[i][k] - m);
                sum += w[i][k];
            }
            const float inv = 1.0f / sum;
            #pragma unroll
            for (int k = 0; k < KS; k++) w[i][k] *= inv;
        }
    }

    // ---- conv: stream 10 input rows, feed 2 accumulators ----
    const float4* in_g =
        (const float4*)(inputs + (size_t)b * S_LEN * D_DIM + h * HD);

    float4 acc[SREG];
    #pragma unroll
    for (int i = 0; i < SREG; i++) acc[i] = make_float4(0.f, 0.f, 0.f, 0.f);

    // row j (global g = s0+sl0-4+j) feeds output i at tap k = j - i
    #pragma unroll
    for (int j = 0; j < SREG + KS - 1; j++) {
        const int g = s0 + sl0 - (KS / 2) + j;
        float4 r = make_float4(0.f, 0.f, 0.f, 0.f);
        if (g >= 0 && g < S_LEN)
            r = __ldg(&in_g[(size_t)g * ROW_F4 + c]);
        #pragma unroll
        for (int i = 0; i < SREG; i++) {
            const int k = j - i;
            if (k >= 0 && k < KS) {
                const float wv = w[i][k];
                acc[i].x = fmaf(wv, r.x, acc[i].x);
                acc[i].y = fmaf(wv, r.y, acc[i].y);
                acc[i].z = fmaf(wv, r.z, acc[i].z);
                acc[i].w = fmaf(wv, r.w, acc[i].w);
            }
        }
    }

    // ---- store (256B-contiguous per position) ----
    float4* out_g = (float4*)(out + (size_t)b * S_LEN * D_DIM + h * HD);
    #pragma unroll
    for (int i = 0; i < SREG; i++)
        out_g[(size_t)(s0 + sl0 + i) * ROW_F4 + c] = acc[i];
}

extern "C" void kernel_launch(void* const* d_in, const int* in_sizes, int n_in,
                              void* d_out, int out_size)
{
    const float* inputs  = (const float*)d_in[0];
    const float* filters = (const float*)d_in[1];
    if (n_in >= 2 && in_sizes[0] == 8 * 4096 * (H_NUM * KS)) {
        filters = (const float*)d_in[0];
        inputs  = (const float*)d_in[1];
    }
    float* out = (float*)d_out;

    dim3 grid(S_LEN / TILE_S, H_NUM, 8);   // 64 x 12 x 8 = 6144 CTAs
    lightconv_kernel<<<grid, NTHREADS>>>(inputs, filters, out);
}

// round 7
// speedup vs baseline: 1.4179x; 1.4179x over previous
#include <cuda_runtime.h>

// ConvBertLightConv: dynamic depthwise conv, kernel=9, head=64.
// inputs:  [B=8, S=4096, D=768] fp32, filters: [B,S,108] fp32, out: [B,S,768].
//
// R6 (from R4 best): hoist all 12 input LDG.128s into registers BEFORE the
// cp.async filter wait, so input DRAM latency overlaps filter staging +
// softmax. 256-thread CTAs with an ~85-reg budget let ptxas front-batch the
// loads (MLP_p1=12). Interior blocks take an unpredicated fast path.

#define S_LEN   4096
#define D_DIM   768
#define H_NUM   12
#define HD      64
#define KS      9
#define TILE_S  64
#define SREG    4
#define NTHREADS 256                 // (TILE_S/SREG)=16 groups x 16 f4-columns
#define NROWS   (SREG + KS - 1)      // 12
#define ROW_F4  (D_DIM / 4)          // 192
#define FP      12                   // padded filter row stride

__device__ __forceinline__ void cp_async16(void* smem, const void* gmem) {
    unsigned sa = (unsigned)__cvta_generic_to_shared(smem);
    asm volatile("cp.async.ca.shared.global [%0], [%1], 16;\n"
                 :: "r"(sa), "l"(gmem));
}

__global__ __launch_bounds__(NTHREADS, 3)
void lightconv_kernel(const float* __restrict__ inputs,
                      const float* __restrict__ filters,
                      float* __restrict__ out)
{
    __shared__ float fraw[TILE_S * FP];   // staged raw taps (aligned window)
    __shared__ float w_s [TILE_S * FP];   // softmaxed taps

    const int tid = threadIdx.x;
    const int s0  = blockIdx.x * TILE_S;
    const int h   = blockIdx.y;
    const int b   = blockIdx.z;

    const int c   = tid & 15;             // float4 column 0..15
    const int sl0 = (tid >> 4) * SREG;    // local base position

    // ---- stage filters: 3 x 16B aligned cp.async per row (192 ops) ----
    const int foff  = h * KS;
    const int a0    = foff & ~3;
    const int shift = foff & 3;
    const float* frow0 = filters + (size_t)(b * S_LEN + s0) * (H_NUM * KS) + a0;

    if (tid < TILE_S * 3) {
        const int r = tid / 3;
        const int q = tid - r * 3;
        cp_async16(&fraw[r * FP + q * 4], frow0 + (size_t)r * (H_NUM * KS) + q * 4);
    }
    asm volatile("cp.async.commit_group;\n" ::: "memory");

    // ---- hoisted input loads: 12 rows into registers, overlap filter wait --
    const float4* in_g =
        (const float4*)(inputs + (size_t)b * S_LEN * D_DIM + h * HD);
    const int gbase = s0 + sl0 - (KS / 2);

    float4 rin[NROWS];
    if (s0 >= (KS / 2) && s0 + TILE_S + (KS / 2) <= S_LEN) {
        // interior fast path: unconditional, front-batched
        #pragma unroll
        for (int j = 0; j < NROWS; j++)
            rin[j] = __ldg(&in_g[(size_t)(gbase + j) * ROW_F4 + c]);
    } else {
        #pragma unroll
        for (int j = 0; j < NROWS; j++) {
            const int g = gbase + j;
            rin[j] = make_float4(0.f, 0.f, 0.f, 0.f);
            if (g >= 0 && g < S_LEN)
                rin[j] = __ldg(&in_g[(size_t)g * ROW_F4 + c]);
        }
    }

    // ---- filters arrive; softmax (2 warps), others' loads still in flight --
    asm volatile("cp.async.wait_group 0;\n" ::: "memory");
    __syncthreads();

    if (tid < TILE_S) {
        float v[KS];
        float m = -1e30f;
        #pragma unroll
        for (int k = 0; k < KS; k++) {
            v[k] = fraw[tid * FP + shift + k];
            m = fmaxf(m, v[k]);
        }
        float sum = 0.f;
        #pragma unroll
        for (int k = 0; k < KS; k++) { v[k] = __expf(v[k] - m); sum += v[k]; }
        const float inv = 1.0f / sum;
        #pragma unroll
        for (int k = 0; k < KS; k++) w_s[tid * FP + k] = v[k] * inv;
    }
    __syncthreads();

    // ---- FMA: row j feeds output i at tap k = j - i ----
    float4 acc[SREG];
    #pragma unroll
    for (int i = 0; i < SREG; i++) acc[i] = make_float4(0.f, 0.f, 0.f, 0.f);

    #pragma unroll
    for (int j = 0; j < NROWS; j++) {
        const float4 r = rin[j];
        #pragma unroll
        for (int i = 0; i < SREG; i++) {
            const int k = j - i;
            if (k >= 0 && k < KS) {
                const float w = w_s[(sl0 + i) * FP + k];
                acc[i].x = fmaf(w, r.x, acc[i].x);
                acc[i].y = fmaf(w, r.y, acc[i].y);
                acc[i].z = fmaf(w, r.z, acc[i].z);
                acc[i].w = fmaf(w, r.w, acc[i].w);
            }
        }
    }

    // ---- store (256B-contiguous per position) ----
    float4* out_g = (float4*)(out + (size_t)b * S_LEN * D_DIM + h * HD);
    #pragma unroll
    for (int i = 0; i < SREG; i++)
        out_g[(size_t)(s0 + sl0 + i) * ROW_F4 + c] = acc[i];
}

extern "C" void kernel_launch(void* const* d_in, const int* in_sizes, int n_in,
                              void* d_out, int out_size)
{
    const float* inputs  = (const float*)d_in[0];
    const float* filters = (const float*)d_in[1];
    if (n_in >= 2 && in_sizes[0] == 8 * 4096 * (H_NUM * KS)) {
        filters = (const float*)d_in[0];
        inputs  = (const float*)d_in[1];
    }
    float* out = (float*)d_out;

    dim3 grid(S_LEN / TILE_S, H_NUM, 8);   // 64 x 12 x 8 = 6144 CTAs
    lightconv_kernel<<<grid, NTHREADS>>>(inputs, filters, out);
}

// round 8
// speedup vs baseline: 1.5133x; 1.0673x over previous
#include <cuda_runtime.h>

// ConvBertLightConv: dynamic depthwise conv, kernel=9, head=64.
// inputs:  [B=8, S=4096, D=768] fp32, filters: [B,S,108] fp32, out: [B,S,768].
//
// R7 (from R6): same structure (front-batched register loads overlapping the
// cp.async filter stage + softmax), but CTA halved to 128 threads / TILE_S=32
// with launch_bounds(128,6): 6 independently-phased CTAs per SM cover each
// other's compute/store DRAM gaps -> higher HBM duty cycle at equal warps.

#define S_LEN   4096
#define D_DIM   768
#define H_NUM   12
#define HD      64
#define KS      9
#define TILE_S  32
#define SREG    4
#define NTHREADS 128                 // (TILE_S/SREG)=8 groups x 16 f4-columns
#define NROWS   (SREG + KS - 1)      // 12
#define ROW_F4  (D_DIM / 4)          // 192
#define FP      12                   // padded filter row stride

__device__ __forceinline__ void cp_async16(void* smem, const void* gmem) {
    unsigned sa = (unsigned)__cvta_generic_to_shared(smem);
    asm volatile("cp.async.ca.shared.global [%0], [%1], 16;\n"
                 :: "r"(sa), "l"(gmem));
}

__global__ __launch_bounds__(NTHREADS, 6)
void lightconv_kernel(const float* __restrict__ inputs,
                      const float* __restrict__ filters,
                      float* __restrict__ out)
{
    __shared__ float fraw[TILE_S * FP];   // staged raw taps (aligned window)
    __shared__ float w_s [TILE_S * FP];   // softmaxed taps

    const int tid = threadIdx.x;
    const int s0  = blockIdx.x * TILE_S;
    const int h   = blockIdx.y;
    const int b   = blockIdx.z;

    const int c   = tid & 15;             // float4 column 0..15
    const int sl0 = (tid >> 4) * SREG;    // local base position

    // ---- stage filters: 3 x 16B aligned cp.async per row (96 ops) ----
    const int foff  = h * KS;
    const int a0    = foff & ~3;
    const int shift = foff & 3;
    const float* frow0 = filters + (size_t)(b * S_LEN + s0) * (H_NUM * KS) + a0;

    if (tid < TILE_S * 3) {
        const int r = tid / 3;
        const int q = tid - r * 3;
        cp_async16(&fraw[r * FP + q * 4], frow0 + (size_t)r * (H_NUM * KS) + q * 4);
    }
    asm volatile("cp.async.commit_group;\n" ::: "memory");

    // ---- hoisted input loads: 12 rows into registers, overlap filter wait --
    const float4* in_g =
        (const float4*)(inputs + (size_t)b * S_LEN * D_DIM + h * HD);
    const int gbase = s0 + sl0 - (KS / 2);

    float4 rin[NROWS];
    if (s0 >= (KS / 2) && s0 + TILE_S + (KS / 2) <= S_LEN) {
        // interior fast path: unconditional, front-batched
        #pragma unroll
        for (int j = 0; j < NROWS; j++)
            rin[j] = __ldg(&in_g[(size_t)(gbase + j) * ROW_F4 + c]);
    } else {
        #pragma unroll
        for (int j = 0; j < NROWS; j++) {
            const int g = gbase + j;
            rin[j] = make_float4(0.f, 0.f, 0.f, 0.f);
            if (g >= 0 && g < S_LEN)
                rin[j] = __ldg(&in_g[(size_t)g * ROW_F4 + c]);
        }
    }

    // ---- filters arrive; softmax (1 warp), other loads still in flight ----
    asm volatile("cp.async.wait_group 0;\n" ::: "memory");
    __syncthreads();

    if (tid < TILE_S) {
        float v[KS];
        float m = -1e30f;
        #pragma unroll
        for (int k = 0; k < KS; k++) {
            v[k] = fraw[tid * FP + shift + k];
            m = fmaxf(m, v[k]);
        }
        float sum = 0.f;
        #pragma unroll
        for (int k = 0; k < KS; k++) { v[k] = __expf(v[k] - m); sum += v[k]; }
        const float inv = 1.0f / sum;
        #pragma unroll
        for (int k = 0; k < KS; k++) w_s[tid * FP + k] = v[k] * inv;
    }
    __syncthreads();

    // ---- FMA: row j feeds output i at tap k = j - i ----
    float4 acc[SREG];
    #pragma unroll
    for (int i = 0; i < SREG; i++) acc[i] = make_float4(0.f, 0.f, 0.f, 0.f);

    #pragma unroll
    for (int j = 0; j < NROWS; j++) {
        const float4 r = rin[j];
        #pragma unroll
        for (int i = 0; i < SREG; i++) {
            const int k = j - i;
            if (k >= 0 && k < KS) {
                const float w = w_s[(sl0 + i) * FP + k];
                acc[i].x = fmaf(w, r.x, acc[i].x);
                acc[i].y = fmaf(w, r.y, acc[i].y);
                acc[i].z = fmaf(w, r.z, acc[i].z);
                acc[i].w = fmaf(w, r.w, acc[i].w);
            }
        }
    }

    // ---- store (256B-contiguous per position) ----
    float4* out_g = (float4*)(out + (size_t)b * S_LEN * D_DIM + h * HD);
    #pragma unroll
    for (int i = 0; i < SREG; i++)
        out_g[(size_t)(s0 + sl0 + i) * ROW_F4 + c] = acc[i];
}

extern "C" void kernel_launch(void* const* d_in, const int* in_sizes, int n_in,
                              void* d_out, int out_size)
{
    const float* inputs  = (const float*)d_in[0];
    const float* filters = (const float*)d_in[1];
    if (n_in >= 2 && in_sizes[0] == 8 * 4096 * (H_NUM * KS)) {
        filters = (const float*)d_in[0];
        inputs  = (const float*)d_in[1];
    }
    float* out = (float*)d_out;

    dim3 grid(S_LEN / TILE_S, H_NUM, 8);   // 128 x 12 x 8 = 12288 CTAs
    lightconv_kernel<<<grid, NTHREADS>>>(inputs, filters, out);
}